// round 1
// baseline (speedup 1.0000x reference)
#include <cuda_runtime.h>
#include <math.h>

#define BB 8
#define CC 64
#define OO 64
#define HH 128
#define WW 128
#define HWSZ (HH*WW)            // 16384
#define NPIX (BB*HWSZ)          // 131072
#define TPB 256

// ---------------- scratch (allocation-free: __device__ globals) --------------
__device__ float g_wmain_t[9*CC*OO];     // [k][c][o]   (o contiguous for f32x2 pairs)
__device__ float g_wom_t[CC*9*28];       // [c][t][j]   j: 0..17 offset, 18..26 mask, 27 pad
__device__ float g_offmask[27*NPIX];     // [j][pixel]; 18..26 already sigmoid'ed

// ---------------- packed f32x2 helpers ---------------------------------------
__device__ __forceinline__ unsigned long long pk2(float lo, float hi){
    unsigned long long r;
    asm("mov.b64 %0, {%1,%2};" : "=l"(r) : "f"(lo), "f"(hi));
    return r;
}
__device__ __forceinline__ void upk2(unsigned long long v, float& lo, float& hi){
    asm("mov.b64 {%0,%1}, %2;" : "=f"(lo), "=f"(hi) : "l"(v));
}
__device__ __forceinline__ unsigned long long f2fma(unsigned long long a,
                                                    unsigned long long b,
                                                    unsigned long long c){
    unsigned long long d;
    asm("fma.rn.f32x2 %0, %1, %2, %3;" : "=l"(d) : "l"(a), "l"(b), "l"(c));
    return d;
}

// ---------------- prep: transpose weights into packed-friendly layouts -------
__global__ void k_prep(const float* __restrict__ wm,
                       const float* __restrict__ wo,
                       const float* __restrict__ wk){
    int i = blockIdx.x*TPB + threadIdx.x;
    if (i < 9*CC*OO){
        int k = i/(CC*OO); int r = i - k*(CC*OO); int c = r/OO; int o = r - c*OO;
        g_wmain_t[i] = wm[(o*CC + c)*9 + k];
    }
    int j2 = i - 9*CC*OO;
    if (j2 >= 0 && j2 < CC*9*28){
        int ct = j2/28; int j = j2 - ct*28; int c = ct/9; int t = ct - c*9;
        float v = 0.f;
        if (j < 18)      v = wo[(j*CC + c)*9 + t];
        else if (j < 27) v = wk[((j-18)*CC + c)*9 + t];
        g_wom_t[j2] = v;
    }
}

// ---------------- kernel 1: offset(18) + mask(9) 3x3 conv, fused ------------
__global__ void __launch_bounds__(TPB)
k_offmask(const float* __restrict__ x,
          const float* __restrict__ boff,
          const float* __restrict__ bmsk){
    __shared__ __align__(16) float s_wom[32*9*28];   // 32 input-ch chunk: 31.5 KB

    int p  = blockIdx.x*TPB + threadIdx.x;
    int b  = p >> 14;
    int hw = p & (HWSZ-1);
    int h  = hw >> 7;
    int w  = hw & (WW-1);
    const float* xb = x + (size_t)b*CC*HWSZ;

    unsigned long long acc[14];
    #pragma unroll
    for (int q=0;q<14;q++){
        int j0=2*q, j1=2*q+1;
        float lo = (j0<18)? boff[j0] : (j0<27 ? bmsk[j0-18] : 0.f);
        float hi = (j1<18)? boff[j1] : (j1<27 ? bmsk[j1-18] : 0.f);
        acc[q] = pk2(lo,hi);
    }

    for (int cc=0; cc<CC; cc+=32){
        __syncthreads();
        for (int i=threadIdx.x; i<32*9*28; i+=TPB)
            s_wom[i] = g_wom_t[cc*9*28 + i];
        __syncthreads();

        for (int c=0;c<32;c++){
            const float* xc = xb + (cc+c)*HWSZ;
            float v[9];
            #pragma unroll
            for (int t=0;t<9;t++){
                int yy = h + t/3 - 1, xx = w + t%3 - 1;
                v[t] = (yy>=0 && yy<HH && xx>=0 && xx<WW) ? __ldg(xc + yy*WW + xx) : 0.f;
            }
            #pragma unroll
            for (int t=0;t<9;t++){
                unsigned long long vv = pk2(v[t], v[t]);
                const ulonglong2* wp = (const ulonglong2*)&s_wom[(c*9+t)*28];
                #pragma unroll
                for (int q=0;q<7;q++){
                    ulonglong2 ww = wp[q];
                    acc[2*q]   = f2fma(vv, ww.x, acc[2*q]);
                    acc[2*q+1] = f2fma(vv, ww.y, acc[2*q+1]);
                }
            }
        }
    }

    #pragma unroll
    for (int q=0;q<14;q++){
        float lo,hi; upk2(acc[q],lo,hi);
        int j0=2*q, j1=2*q+1;
        if (j0<27) g_offmask[j0*NPIX+p] = (j0>=18)? 1.f/(1.f+expf(-lo)) : lo;
        if (j1<27) g_offmask[j1*NPIX+p] = (j1>=18)? 1.f/(1.f+expf(-hi)) : hi;
    }
}

// ---------------- kernel 2: bilinear sampling + 576x64 contraction ----------
__global__ void __launch_bounds__(TPB)
k_main(const float* __restrict__ x, float* __restrict__ out){
    __shared__ __align__(16) float s_w[CC*OO];   // one k-slice: 16 KB, layout [c][o]

    int p  = blockIdx.x*TPB + threadIdx.x;
    int b  = p >> 14;
    int hw = p & (HWSZ-1);
    int h  = hw >> 7;
    int w  = hw & (WW-1);
    const float* xb = x + (size_t)b*CC*HWSZ;

    unsigned long long acc[32];
    #pragma unroll
    for (int q=0;q<32;q++) acc[q] = 0ull;   // (0.f, 0.f)

    for (int k=0;k<9;k++){
        __syncthreads();
        for (int i=threadIdx.x; i<CC*OO; i+=TPB)
            s_w[i] = g_wmain_t[k*CC*OO + i];
        __syncthreads();

        float dy = g_offmask[(2*k  )*NPIX + p];
        float dx = g_offmask[(2*k+1)*NPIX + p];
        float mk = g_offmask[(18+k )*NPIX + p];

        float py = dy + (float)(h + k/3 - 1);
        float px = dx + (float)(w + k%3 - 1);
        float y0f = floorf(py), x0f = floorf(px);
        float ly = py - y0f,   lx = px - x0f;
        int y0 = (int)y0f, x0 = (int)x0f;
        int y1 = y0 + 1,   x1 = x0 + 1;

        float vy0 = (y0>=0 && y0<HH) ? 1.f : 0.f;
        float vy1 = (y1>=0 && y1<HH) ? 1.f : 0.f;
        float vx0 = (x0>=0 && x0<WW) ? 1.f : 0.f;
        float vx1 = (x1>=0 && x1<WW) ? 1.f : 0.f;

        float w00 = (1.f-ly)*(1.f-lx)*vy0*vx0*mk;
        float w01 = (1.f-ly)*lx      *vy0*vx1*mk;
        float w10 = ly      *(1.f-lx)*vy1*vx0*mk;
        float w11 = ly      *lx      *vy1*vx1*mk;

        int y0c = min(max(y0,0),HH-1), y1c = min(max(y1,0),HH-1);
        int x0c = min(max(x0,0),WW-1), x1c = min(max(x1,0),WW-1);
        int a00 = y0c*WW + x0c, a01 = y0c*WW + x1c;
        int a10 = y1c*WW + x0c, a11 = y1c*WW + x1c;

        for (int c=0;c<CC;c++){
            const float* xc = xb + c*HWSZ;
            float v = w00*__ldg(xc+a00) + w01*__ldg(xc+a01)
                    + w10*__ldg(xc+a10) + w11*__ldg(xc+a11);
            unsigned long long vv = pk2(v, v);
            const ulonglong2* wp = (const ulonglong2*)&s_w[c*OO];
            #pragma unroll
            for (int q=0;q<16;q++){
                ulonglong2 ww = wp[q];
                acc[2*q]   = f2fma(vv, ww.x, acc[2*q]);
                acc[2*q+1] = f2fma(vv, ww.y, acc[2*q+1]);
            }
        }
    }

    float* ob = out + (size_t)b*OO*HWSZ + hw;
    #pragma unroll
    for (int q=0;q<32;q++){
        float lo,hi; upk2(acc[q],lo,hi);
        ob[(2*q  )*HWSZ] = lo;
        ob[(2*q+1)*HWSZ] = hi;
    }
}

// ---------------- launch ------------------------------------------------------
extern "C" void kernel_launch(void* const* d_in, const int* in_sizes, int n_in,
                              void* d_out, int out_size){
    const float* x        = (const float*)d_in[0];
    const float* w_main   = (const float*)d_in[1];
    const float* w_offset = (const float*)d_in[2];
    const float* b_offset = (const float*)d_in[3];
    const float* w_mask   = (const float*)d_in[4];
    const float* b_mask   = (const float*)d_in[5];
    float* out = (float*)d_out;

    int prep_n = 9*CC*OO + CC*9*28;
    k_prep<<<(prep_n + TPB-1)/TPB, TPB>>>(w_main, w_offset, w_mask);
    k_offmask<<<NPIX/TPB, TPB>>>(x, b_offset, b_mask);
    k_main<<<NPIX/TPB, TPB>>>(x, out);
}

// round 2
// speedup vs baseline: 1.1150x; 1.1150x over previous
#include <cuda_runtime.h>
#include <math.h>

#define BB 8
#define CC 64
#define OO 64
#define HH 128
#define WW 128
#define HWSZ (HH*WW)            // 16384
#define NPIX (BB*HWSZ)          // 131072
#define TPB 256

typedef unsigned long long ull;

// ---------------- scratch (allocation-free: __device__ globals) --------------
__device__ float  g_wom_t[CC*9*28];            // [c][t][j] j:0..17 offset,18..26 mask,27 pad
__device__ float  g_Wt[CC*576];                // [c][k*64+o]
__device__ float4 g_cw4[(size_t)NPIX*9];       // per (p,k): 4 corner weights (mask folded)
__device__ int4   g_ci4[(size_t)NPIX*9];       // per (p,k): 4 clamped hw indices
__device__ float  g_Y[(size_t)9*NPIX*OO];      // [b][k][hw][o]  (302 MB scratch)

// ---------------- packed f32x2 helpers ---------------------------------------
__device__ __forceinline__ ull pk2(float lo, float hi){
    ull r; asm("mov.b64 %0, {%1,%2};" : "=l"(r) : "f"(lo), "f"(hi)); return r;
}
__device__ __forceinline__ void upk2(ull v, float& lo, float& hi){
    asm("mov.b64 {%0,%1}, %2;" : "=f"(lo), "=f"(hi) : "l"(v));
}
__device__ __forceinline__ ull f2fma(ull a, ull b, ull c){
    ull d; asm("fma.rn.f32x2 %0, %1, %2, %3;" : "=l"(d) : "l"(a), "l"(b), "l"(c)); return d;
}
__device__ __forceinline__ ull ldg2(const float* p){
    ull v; asm("ld.global.nc.b64 %0, [%1];" : "=l"(v) : "l"(p)); return v;
}

// ---------------- prep: transpose weights ------------------------------------
__global__ void k_prep(const float* __restrict__ wm,
                       const float* __restrict__ wo,
                       const float* __restrict__ wk){
    int i = blockIdx.x*TPB + threadIdx.x;
    if (i < CC*576){                       // g_Wt[c][k*64+o] = wm[o,c,k]
        int c = i/576; int r = i - c*576; int k = r/64; int o = r - k*64;
        g_Wt[i] = wm[(o*CC + c)*9 + k];
    }
    int j2 = i - CC*576;
    if (j2 >= 0 && j2 < CC*9*28){
        int ct = j2/28; int j = j2 - ct*28; int c = ct/9; int t = ct - c*9;
        float v = 0.f;
        if (j < 18)      v = wo[(j*CC + c)*9 + t];
        else if (j < 27) v = wk[((j-18)*CC + c)*9 + t];
        g_wom_t[j2] = v;
    }
}

// ---- P1: offset(18)+mask(9) 3x3 conv, fused; emit folded corner wgts/idx ----
__global__ void __launch_bounds__(TPB)
k_offmask(const float* __restrict__ x,
          const float* __restrict__ boff,
          const float* __restrict__ bmsk){
    __shared__ __align__(16) float s_wom[32*9*28];   // 31.5 KB

    int p   = blockIdx.x*TPB + threadIdx.x;
    int b   = p >> 14;
    int hw  = p & (HWSZ-1);
    int h   = hw >> 7;
    int wp  = hw & (WW-1);
    const float* xb = x + (size_t)b*CC*HWSZ;

    ull acc[14];
    #pragma unroll
    for (int q=0;q<14;q++){
        int j0=2*q, j1=2*q+1;
        float lo = (j0<18)? boff[j0] : (j0<27 ? bmsk[j0-18] : 0.f);
        float hi = (j1<18)? boff[j1] : (j1<27 ? bmsk[j1-18] : 0.f);
        acc[q] = pk2(lo,hi);
    }

    for (int cc=0; cc<CC; cc+=32){
        __syncthreads();
        for (int i=threadIdx.x; i<32*9*28; i+=TPB)
            s_wom[i] = g_wom_t[cc*9*28 + i];
        __syncthreads();

        for (int c=0;c<32;c++){
            const float* xc = xb + (cc+c)*HWSZ;
            float v[9];
            #pragma unroll
            for (int t=0;t<9;t++){
                int yy = h + t/3 - 1, xx = wp + t%3 - 1;
                v[t] = (yy>=0 && yy<HH && xx>=0 && xx<WW) ? __ldg(xc + yy*WW + xx) : 0.f;
            }
            #pragma unroll
            for (int t=0;t<9;t++){
                ull vv = pk2(v[t], v[t]);
                const ulonglong2* wq = (const ulonglong2*)&s_wom[(c*9+t)*28];
                #pragma unroll
                for (int q=0;q<7;q++){
                    ulonglong2 ww = wq[q];
                    acc[2*q]   = f2fma(vv, ww.x, acc[2*q]);
                    acc[2*q+1] = f2fma(vv, ww.y, acc[2*q+1]);
                }
            }
        }
    }

    // epilogue: fold sigmoid(mask) + bilinear validity into 4 corner weights
    #pragma unroll
    for (int k=0;k<9;k++){
        float dy, dx; upk2(acc[k], dy, dx);
        float mlo, mhi; upk2(acc[9 + k/2], mlo, mhi);
        float mraw = (k & 1) ? mhi : mlo;
        float mk = 1.f/(1.f + expf(-mraw));

        float py = dy + (float)(h + k/3 - 1);
        float px = dx + (float)(wp + k%3 - 1);
        float y0f = floorf(py), x0f = floorf(px);
        float ly = py - y0f, lx = px - x0f;
        int y0 = (int)y0f, x0 = (int)x0f;
        int y1 = y0 + 1,   x1 = x0 + 1;

        float vy0 = (y0>=0 && y0<HH) ? 1.f : 0.f;
        float vy1 = (y1>=0 && y1<HH) ? 1.f : 0.f;
        float vx0 = (x0>=0 && x0<WW) ? 1.f : 0.f;
        float vx1 = (x1>=0 && x1<WW) ? 1.f : 0.f;

        float w00 = (1.f-ly)*(1.f-lx)*vy0*vx0*mk;
        float w01 = (1.f-ly)*lx      *vy0*vx1*mk;
        float w10 = ly      *(1.f-lx)*vy1*vx0*mk;
        float w11 = ly      *lx      *vy1*vx1*mk;

        int y0c = min(max(y0,0),HH-1), y1c = min(max(y1,0),HH-1);
        int x0c = min(max(x0,0),WW-1), x1c = min(max(x1,0),WW-1);

        g_cw4[(size_t)p*9 + k] = make_float4(w00,w01,w10,w11);
        g_ci4[(size_t)p*9 + k] = make_int4(y0c*WW+x0c, y0c*WW+x1c,
                                           y1c*WW+x0c, y1c*WW+x1c);
    }
}

// ---- P2: dense GEMM  Y[p, k*64+o] = sum_c x[b,c,hw] * Wt[c][k*64+o] ---------
// grid (1024, 9); CTA tile = 128 px × 64 n (n-tile == one k), K = 64.
__global__ void __launch_bounds__(TPB)
k_gemm(const float* __restrict__ x){
    __shared__ __align__(16) float A_s[64][128];   // [c][px]  32 KB
    __shared__ __align__(16) float B_s[64][64];    // [c][n]   16 KB

    int k    = blockIdx.y;
    int pblk = blockIdx.x;
    int b    = (pblk*128) >> 14;
    int hw0  = (pblk*128) & (HWSZ-1);
    const float* xb = x + (size_t)b*CC*HWSZ + hw0;

    int t = threadIdx.x, lane = t & 31, w = t >> 5;

    for (int c = w; c < 64; c += 8)
        *(float4*)&A_s[c][lane*4] = *(const float4*)(xb + (size_t)c*HWSZ + lane*4);
    for (int c = w; c < 64; c += 8)
        *(float2*)&B_s[c][lane*2] = *(const float2*)(g_Wt + c*576 + k*64 + lane*2);
    __syncthreads();

    int tx = t & 15;      // 4 n each
    int ty = t >> 4;      // 8 px each

    ull acc[8][2];
    #pragma unroll
    for (int i=0;i<8;i++){ acc[i][0]=0ull; acc[i][1]=0ull; }

    #pragma unroll 8
    for (int kk=0; kk<64; kk++){
        float a0[4], a1[4];
        *(float4*)a0 = *(float4*)&A_s[kk][ty*8];
        *(float4*)a1 = *(float4*)&A_s[kk][ty*8+4];
        float4 bv = *(float4*)&B_s[kk][tx*4];
        ull b0 = pk2(bv.x, bv.y);
        ull b1 = pk2(bv.z, bv.w);
        #pragma unroll
        for (int i=0;i<4;i++){
            ull av = pk2(a0[i], a0[i]);
            acc[i][0] = f2fma(av, b0, acc[i][0]);
            acc[i][1] = f2fma(av, b1, acc[i][1]);
        }
        #pragma unroll
        for (int i=0;i<4;i++){
            ull av = pk2(a1[i], a1[i]);
            acc[4+i][0] = f2fma(av, b0, acc[4+i][0]);
            acc[4+i][1] = f2fma(av, b1, acc[4+i][1]);
        }
    }

    float* Yp = g_Y + ((size_t)(b*9 + k)*HWSZ + hw0) * OO;
    #pragma unroll
    for (int i=0;i<8;i++){
        float l0,h0,l1,h1;
        upk2(acc[i][0], l0, h0);
        upk2(acc[i][1], l1, h1);
        *(float4*)(Yp + (size_t)(ty*8+i)*OO + tx*4) = make_float4(l0,h0,l1,h1);
    }
}

// ---- P3: gather-combine: out[p,o] = sum_k sum_corner w·Y[b,k,idx,o] ---------
// warp handles 32 consecutive pixels; lane owns o-pair (2l, 2l+1).
__global__ void __launch_bounds__(TPB)
k_gather(float* __restrict__ out){
    __shared__ float tile[8][16][66];   // per-warp transpose staging, 33 KB

    int w  = threadIdx.x >> 5;
    int l  = threadIdx.x & 31;
    int p0 = blockIdx.x*256 + w*32;
    int b  = p0 >> 14;
    const float* Yb = g_Y + (size_t)b*9*HWSZ*OO + 2*l;

    for (int half=0; half<2; half++){
        #pragma unroll 1
        for (int i=0;i<16;i++){
            int p = p0 + half*16 + i;
            const float4* cw = (const float4*)&g_cw4[(size_t)p*9];
            const int4*   ci = (const int4*)  &g_ci4[(size_t)p*9];
            ull accp = 0ull;
            #pragma unroll
            for (int k=0;k<9;k++){
                float4 wq = __ldg(&cw[k]);
                int4   iq = __ldg(&ci[k]);
                const float* Yk = Yb + (size_t)k*HWSZ*OO;
                accp = f2fma(pk2(wq.x,wq.x), ldg2(Yk + (size_t)iq.x*OO), accp);
                accp = f2fma(pk2(wq.y,wq.y), ldg2(Yk + (size_t)iq.y*OO), accp);
                accp = f2fma(pk2(wq.z,wq.z), ldg2(Yk + (size_t)iq.z*OO), accp);
                accp = f2fma(pk2(wq.w,wq.w), ldg2(Yk + (size_t)iq.w*OO), accp);
            }
            float lo, hi; upk2(accp, lo, hi);
            tile[w][i][2*l]   = lo;
            tile[w][i][2*l+1] = hi;
        }
        __syncwarp();
        int hwc = (p0 & (HWSZ-1)) + half*16;
        int px  = l & 15;
        #pragma unroll 8
        for (int o2=0;o2<32;o2++){
            int o = o2*2 + (l>>4);
            out[((size_t)(b*OO + o))*HWSZ + hwc + px] = tile[w][px][o];
        }
        __syncwarp();
    }
}

// ---------------- launch ------------------------------------------------------
extern "C" void kernel_launch(void* const* d_in, const int* in_sizes, int n_in,
                              void* d_out, int out_size){
    const float* x        = (const float*)d_in[0];
    const float* w_main   = (const float*)d_in[1];
    const float* w_offset = (const float*)d_in[2];
    const float* b_offset = (const float*)d_in[3];
    const float* w_mask   = (const float*)d_in[4];
    const float* b_mask   = (const float*)d_in[5];
    float* out = (float*)d_out;

    int prep_n = CC*576 + CC*9*28;
    k_prep<<<(prep_n + TPB-1)/TPB, TPB>>>(w_main, w_offset, w_mask);
    k_offmask<<<NPIX/TPB, TPB>>>(x, b_offset, b_mask);
    dim3 gg(NPIX/128, 9);
    k_gemm<<<gg, TPB>>>(x);
    k_gather<<<NPIX/256, TPB>>>(out);
}